// round 1
// baseline (speedup 1.0000x reference)
#include <cuda_runtime.h>
#include <math.h>
#include <stdint.h>

#define T_TOK 4096
#define D_DIM 1024
#define E_NUM 8
#define H_DIM 2816

// ---------------- scratch (__device__ globals: allocation-free) ----------------
__device__ int   g_cnt[E_NUM];
__device__ int   g_slot_tok[E_NUM * T_TOK];   // token id per (expert, slot)
__device__ float g_slot_w[E_NUM * T_TOK];     // combine weight per slot
__device__ int   g_tok_slot[T_TOK * 2];       // per token: flat slot = e*T + s
__device__ float g_h[(size_t)E_NUM * T_TOK * H_DIM];    // SwiGLU activations (369 MB)
__device__ float g_down[(size_t)E_NUM * T_TOK * D_DIM]; // per-slot down-proj (128 MB)

// ---------------- reset ----------------
__global__ void zero_cnt_kernel() {
    if (threadIdx.x < E_NUM) g_cnt[threadIdx.x] = 0;
}

// ---------------- gating: logits -> exp -> top2 -> slot append ----------------
__global__ __launch_bounds__(256) void gating_kernel(const float* __restrict__ x,
                                                     const float* __restrict__ wg) {
    __shared__ float s_red[E_NUM][256];
    const int t   = blockIdx.x;
    const int tid = threadIdx.x;
    const float* xr = x + (size_t)t * D_DIM;

    float part[E_NUM];
#pragma unroll
    for (int e = 0; e < E_NUM; e++) part[e] = 0.f;

    for (int d = tid; d < D_DIM; d += 256) {
        const float xv = xr[d];
        const float* w = wg + (size_t)d * E_NUM;
#pragma unroll
        for (int e = 0; e < E_NUM; e++) part[e] += xv * w[e];
    }
#pragma unroll
    for (int e = 0; e < E_NUM; e++) s_red[e][tid] = part[e];
    __syncthreads();

    for (int s = 128; s > 0; s >>= 1) {
        if (tid < s) {
#pragma unroll
            for (int e = 0; e < E_NUM; e++) s_red[e][tid] += s_red[e][tid + s];
        }
        __syncthreads();
    }

    if (tid == 0) {
        float l[E_NUM], p[E_NUM];
        float mx = -1e30f;
#pragma unroll
        for (int e = 0; e < E_NUM; e++) { l[e] = s_red[e][0]; mx = fmaxf(mx, l[e]); }
#pragma unroll
        for (int e = 0; e < E_NUM; e++) p[e] = expf(l[e] - mx);

        // top-2, strict > keeps earliest index (matches jax.lax.top_k ties)
        int i1 = 0;
#pragma unroll
        for (int e = 1; e < E_NUM; e++) if (p[e] > p[i1]) i1 = e;
        int i2 = (i1 == 0) ? 1 : 0;
#pragma unroll
        for (int e = 0; e < E_NUM; e++) if (e != i1 && p[e] > p[i2]) i2 = e;

        const float wsum = p[i1] + p[i2];
        const float w1n = p[i1] / wsum;
        const float w2n = p[i2] / wsum;

        const int s0 = atomicAdd(&g_cnt[i1], 1);
        const int s1 = atomicAdd(&g_cnt[i2], 1);
        g_slot_tok[i1 * T_TOK + s0] = t;
        g_slot_w  [i1 * T_TOK + s0] = w1n;
        g_slot_tok[i2 * T_TOK + s1] = t;
        g_slot_w  [i2 * T_TOK + s1] = w2n;
        g_tok_slot[2 * t + 0] = i1 * T_TOK + s0;
        g_tok_slot[2 * t + 1] = i2 * T_TOK + s1;
    }
}

// ---------------- fused gate/up GEMM + SwiGLU ----------------
// Per expert: H_out[m, n] = silu(X[m]@w1[e]) * (X[m]@w3[e]), gathered rows.
// Tile: BM=128, BN=64, BK=16. 256 threads, 8x4 microtile, dual accumulators.
__global__ __launch_bounds__(256) void gemm13_kernel(const float* __restrict__ x,
                                                     const float* __restrict__ w1,
                                                     const float* __restrict__ w3) {
    const int e   = blockIdx.z;
    const int cnt = g_cnt[e];
    const int m0  = blockIdx.y * 128;
    if (m0 >= cnt) return;
    const int n0  = blockIdx.x * 64;

    __shared__ float As[16][128];
    __shared__ float B1s[16][64];
    __shared__ float B3s[16][64];
    __shared__ int   s_row[128];

    const int tid = threadIdx.x;
    if (tid < 128) {
        int m = m0 + tid;
        s_row[tid] = g_slot_tok[e * T_TOK + (m < cnt ? m : cnt - 1)];
    }
    __syncthreads();

    // A load mapping: each thread loads 8 contiguous floats of one row
    const int ar  = tid >> 1;            // row within tile 0..127
    const int ac0 = (tid & 1) * 8;       // k-offset 0 or 8
    const float* xrow = x + (size_t)s_row[ar] * D_DIM + ac0;

    // B load mapping: one float4 per thread per matrix
    const int br = tid >> 4;             // k-row 0..15
    const int bc = tid & 15;             // float4 col 0..15
    const float* w1p = w1 + ((size_t)e * D_DIM + br) * H_DIM + n0 + bc * 4;
    const float* w3p = w3 + ((size_t)e * D_DIM + br) * H_DIM + n0 + bc * 4;

    const int tm = tid >> 4;             // 0..15 (8 rows each)
    const int tn = tid & 15;             // 0..15 (4 cols each)

    float acc1[8][4], acc3[8][4];
#pragma unroll
    for (int i = 0; i < 8; i++)
#pragma unroll
        for (int j = 0; j < 4; j++) { acc1[i][j] = 0.f; acc3[i][j] = 0.f; }

    for (int k0 = 0; k0 < D_DIM; k0 += 16) {
        const float4 va  = *(const float4*)(xrow + k0);
        const float4 vb  = *(const float4*)(xrow + k0 + 4);
        const float4 b1v = *(const float4*)(w1p + (size_t)k0 * H_DIM);
        const float4 b3v = *(const float4*)(w3p + (size_t)k0 * H_DIM);

        __syncthreads();  // previous iteration's compute done
        As[ac0 + 0][ar] = va.x; As[ac0 + 1][ar] = va.y;
        As[ac0 + 2][ar] = va.z; As[ac0 + 3][ar] = va.w;
        As[ac0 + 4][ar] = vb.x; As[ac0 + 5][ar] = vb.y;
        As[ac0 + 6][ar] = vb.z; As[ac0 + 7][ar] = vb.w;
        *(float4*)&B1s[br][bc * 4] = b1v;
        *(float4*)&B3s[br][bc * 4] = b3v;
        __syncthreads();

#pragma unroll
        for (int k = 0; k < 16; k++) {
            float a[8], b1[4], b3[4];
            *(float4*)&a[0] = *(const float4*)&As[k][tm * 8];
            *(float4*)&a[4] = *(const float4*)&As[k][tm * 8 + 4];
            *(float4*)&b1[0] = *(const float4*)&B1s[k][tn * 4];
            *(float4*)&b3[0] = *(const float4*)&B3s[k][tn * 4];
#pragma unroll
            for (int i = 0; i < 8; i++)
#pragma unroll
                for (int j = 0; j < 4; j++) {
                    acc1[i][j] += a[i] * b1[j];
                    acc3[i][j] += a[i] * b3[j];
                }
        }
    }

    float* hbase = g_h + (size_t)e * T_TOK * H_DIM;
#pragma unroll
    for (int i = 0; i < 8; i++) {
        const int m = m0 + tm * 8 + i;
        if (m < cnt) {
            float4 hv;
            float g, u;
            g = acc1[i][0]; u = acc3[i][0]; hv.x = (g / (1.f + expf(-g))) * u;
            g = acc1[i][1]; u = acc3[i][1]; hv.y = (g / (1.f + expf(-g))) * u;
            g = acc1[i][2]; u = acc3[i][2]; hv.z = (g / (1.f + expf(-g))) * u;
            g = acc1[i][3]; u = acc3[i][3]; hv.w = (g / (1.f + expf(-g))) * u;
            *(float4*)&hbase[(size_t)m * H_DIM + n0 + tn * 4] = hv;
        }
    }
}

// ---------------- down-proj GEMM with combine-weight epilogue ----------------
// Per expert: down[m, n] = w_m * (H[m] @ w2[e]),  K = H_DIM.
__global__ __launch_bounds__(256) void gemm2_kernel(const float* __restrict__ w2) {
    const int e   = blockIdx.z;
    const int cnt = g_cnt[e];
    const int m0  = blockIdx.y * 128;
    if (m0 >= cnt) return;
    const int n0  = blockIdx.x * 64;

    __shared__ float As[16][128];
    __shared__ float Bs[16][64];

    const int tid = threadIdx.x;
    const int ar  = tid >> 1;
    const int ac0 = (tid & 1) * 8;
    const int mrow = (m0 + ar < cnt) ? (m0 + ar) : (cnt - 1);
    const float* hrow = g_h + ((size_t)e * T_TOK + mrow) * H_DIM + ac0;

    const int br = tid >> 4;
    const int bc = tid & 15;
    const float* w2p = w2 + ((size_t)e * H_DIM + br) * D_DIM + n0 + bc * 4;

    const int tm = tid >> 4;
    const int tn = tid & 15;

    float acc[8][4];
#pragma unroll
    for (int i = 0; i < 8; i++)
#pragma unroll
        for (int j = 0; j < 4; j++) acc[i][j] = 0.f;

    for (int k0 = 0; k0 < H_DIM; k0 += 16) {
        const float4 va = *(const float4*)(hrow + k0);
        const float4 vb = *(const float4*)(hrow + k0 + 4);
        const float4 bv = *(const float4*)(w2p + (size_t)k0 * D_DIM);

        __syncthreads();
        As[ac0 + 0][ar] = va.x; As[ac0 + 1][ar] = va.y;
        As[ac0 + 2][ar] = va.z; As[ac0 + 3][ar] = va.w;
        As[ac0 + 4][ar] = vb.x; As[ac0 + 5][ar] = vb.y;
        As[ac0 + 6][ar] = vb.z; As[ac0 + 7][ar] = vb.w;
        *(float4*)&Bs[br][bc * 4] = bv;
        __syncthreads();

#pragma unroll
        for (int k = 0; k < 16; k++) {
            float a[8], b[4];
            *(float4*)&a[0] = *(const float4*)&As[k][tm * 8];
            *(float4*)&a[4] = *(const float4*)&As[k][tm * 8 + 4];
            *(float4*)&b[0] = *(const float4*)&Bs[k][tn * 4];
#pragma unroll
            for (int i = 0; i < 8; i++)
#pragma unroll
                for (int j = 0; j < 4; j++) acc[i][j] += a[i] * b[j];
        }
    }

#pragma unroll
    for (int i = 0; i < 8; i++) {
        const int m = m0 + tm * 8 + i;
        if (m < cnt) {
            const float wgt = g_slot_w[e * T_TOK + m];
            float4 ov;
            ov.x = acc[i][0] * wgt; ov.y = acc[i][1] * wgt;
            ov.z = acc[i][2] * wgt; ov.w = acc[i][3] * wgt;
            *(float4*)&g_down[((size_t)e * T_TOK + m) * D_DIM + n0 + tn * 4] = ov;
        }
    }
}

// ---------------- combine: out[t] = down[slot0] + down[slot1] ----------------
__global__ __launch_bounds__(256) void combine_kernel(float* __restrict__ out) {
    const int t = blockIdx.x;
    const int i = threadIdx.x;  // D/4 = 256 float4 per token
    const int s0 = g_tok_slot[2 * t + 0];
    const int s1 = g_tok_slot[2 * t + 1];
    const float4 a = *(const float4*)(g_down + (size_t)s0 * D_DIM + i * 4);
    const float4 b = *(const float4*)(g_down + (size_t)s1 * D_DIM + i * 4);
    float4 o;
    o.x = a.x + b.x; o.y = a.y + b.y; o.z = a.z + b.z; o.w = a.w + b.w;
    *(float4*)(out + (size_t)t * D_DIM + i * 4) = o;
}

// ---------------- launch ----------------
extern "C" void kernel_launch(void* const* d_in, const int* in_sizes, int n_in,
                              void* d_out, int out_size) {
    const float* x  = (const float*)d_in[0];
    const float* wg = (const float*)d_in[1];
    const float* w1 = (const float*)d_in[2];
    const float* w2 = (const float*)d_in[3];
    const float* w3 = (const float*)d_in[4];
    float* out = (float*)d_out;

    zero_cnt_kernel<<<1, 32>>>();
    gating_kernel<<<T_TOK, 256>>>(x, wg);
    gemm13_kernel<<<dim3(H_DIM / 64, T_TOK / 128, E_NUM), 256>>>(x, w1, w3);
    gemm2_kernel<<<dim3(D_DIM / 64, T_TOK / 128, E_NUM), 256>>>(w2);
    combine_kernel<<<T_TOK, 256>>>(out);
}

// round 2
// speedup vs baseline: 1.0002x; 1.0002x over previous
#include <cuda_runtime.h>
#include <math.h>
#include <stdint.h>

#define T_TOK 4096
#define D_DIM 1024
#define E_NUM 8
#define H_DIM 2816

// ---------------- scratch (__device__ globals: allocation-free) ----------------
__device__ int   g_cnt[E_NUM];
__device__ int   g_slot_tok[E_NUM * T_TOK];   // token id per (expert, slot)
__device__ float g_slot_w[E_NUM * T_TOK];     // combine weight per slot
__device__ int   g_tok_slot[T_TOK * 2];       // per token: flat slot = e*T + s
__device__ float g_h[(size_t)E_NUM * T_TOK * H_DIM];    // SwiGLU activations (369 MB)
__device__ float g_down[(size_t)E_NUM * T_TOK * D_DIM]; // per-slot down-proj (128 MB)

// ---------------- reset ----------------
__global__ void zero_cnt_kernel() {
    if (threadIdx.x < E_NUM) g_cnt[threadIdx.x] = 0;
}

// ---------------- gating: logits -> exp -> top2 -> slot append ----------------
__global__ __launch_bounds__(256) void gating_kernel(const float* __restrict__ x,
                                                     const float* __restrict__ wg) {
    __shared__ float s_red[E_NUM][256];
    const int t   = blockIdx.x;
    const int tid = threadIdx.x;
    const float* xr = x + (size_t)t * D_DIM;

    float part[E_NUM];
#pragma unroll
    for (int e = 0; e < E_NUM; e++) part[e] = 0.f;

    for (int d = tid; d < D_DIM; d += 256) {
        const float xv = xr[d];
        const float* w = wg + (size_t)d * E_NUM;
#pragma unroll
        for (int e = 0; e < E_NUM; e++) part[e] += xv * w[e];
    }
#pragma unroll
    for (int e = 0; e < E_NUM; e++) s_red[e][tid] = part[e];
    __syncthreads();

    for (int s = 128; s > 0; s >>= 1) {
        if (tid < s) {
#pragma unroll
            for (int e = 0; e < E_NUM; e++) s_red[e][tid] += s_red[e][tid + s];
        }
        __syncthreads();
    }

    if (tid == 0) {
        float l[E_NUM], p[E_NUM];
        float mx = -1e30f;
#pragma unroll
        for (int e = 0; e < E_NUM; e++) { l[e] = s_red[e][0]; mx = fmaxf(mx, l[e]); }
#pragma unroll
        for (int e = 0; e < E_NUM; e++) p[e] = expf(l[e] - mx);

        // top-2, strict > keeps earliest index (matches jax.lax.top_k ties)
        int i1 = 0;
#pragma unroll
        for (int e = 1; e < E_NUM; e++) if (p[e] > p[i1]) i1 = e;
        int i2 = (i1 == 0) ? 1 : 0;
#pragma unroll
        for (int e = 0; e < E_NUM; e++) if (e != i1 && p[e] > p[i2]) i2 = e;

        const float wsum = p[i1] + p[i2];
        const float w1n = p[i1] / wsum;
        const float w2n = p[i2] / wsum;

        const int s0 = atomicAdd(&g_cnt[i1], 1);
        const int s1 = atomicAdd(&g_cnt[i2], 1);
        g_slot_tok[i1 * T_TOK + s0] = t;
        g_slot_w  [i1 * T_TOK + s0] = w1n;
        g_slot_tok[i2 * T_TOK + s1] = t;
        g_slot_w  [i2 * T_TOK + s1] = w2n;
        g_tok_slot[2 * t + 0] = i1 * T_TOK + s0;
        g_tok_slot[2 * t + 1] = i2 * T_TOK + s1;
    }
}

// ---------------- fused gate/up GEMM + SwiGLU ----------------
// Per expert: H_out[m, n] = silu(X[m]@w1[e]) * (X[m]@w3[e]), gathered rows.
// Tile: BM=128, BN=64, BK=16. 256 threads, 8x4 microtile, dual accumulators.
__global__ __launch_bounds__(256) void gemm13_kernel(const float* __restrict__ x,
                                                     const float* __restrict__ w1,
                                                     const float* __restrict__ w3) {
    const int e   = blockIdx.z;
    const int cnt = g_cnt[e];
    const int m0  = blockIdx.y * 128;
    if (m0 >= cnt) return;
    const int n0  = blockIdx.x * 64;

    __shared__ float As[16][128];
    __shared__ float B1s[16][64];
    __shared__ float B3s[16][64];
    __shared__ int   s_row[128];

    const int tid = threadIdx.x;
    if (tid < 128) {
        int m = m0 + tid;
        s_row[tid] = g_slot_tok[e * T_TOK + (m < cnt ? m : cnt - 1)];
    }
    __syncthreads();

    // A load mapping: each thread loads 8 contiguous floats of one row
    const int ar  = tid >> 1;            // row within tile 0..127
    const int ac0 = (tid & 1) * 8;       // k-offset 0 or 8
    const float* xrow = x + (size_t)s_row[ar] * D_DIM + ac0;

    // B load mapping: one float4 per thread per matrix
    const int br = tid >> 4;             // k-row 0..15
    const int bc = tid & 15;             // float4 col 0..15
    const float* w1p = w1 + ((size_t)e * D_DIM + br) * H_DIM + n0 + bc * 4;
    const float* w3p = w3 + ((size_t)e * D_DIM + br) * H_DIM + n0 + bc * 4;

    const int tm = tid >> 4;             // 0..15 (8 rows each)
    const int tn = tid & 15;             // 0..15 (4 cols each)

    float acc1[8][4], acc3[8][4];
#pragma unroll
    for (int i = 0; i < 8; i++)
#pragma unroll
        for (int j = 0; j < 4; j++) { acc1[i][j] = 0.f; acc3[i][j] = 0.f; }

    for (int k0 = 0; k0 < D_DIM; k0 += 16) {
        const float4 va  = *(const float4*)(xrow + k0);
        const float4 vb  = *(const float4*)(xrow + k0 + 4);
        const float4 b1v = *(const float4*)(w1p + (size_t)k0 * H_DIM);
        const float4 b3v = *(const float4*)(w3p + (size_t)k0 * H_DIM);

        __syncthreads();  // previous iteration's compute done
        As[ac0 + 0][ar] = va.x; As[ac0 + 1][ar] = va.y;
        As[ac0 + 2][ar] = va.z; As[ac0 + 3][ar] = va.w;
        As[ac0 + 4][ar] = vb.x; As[ac0 + 5][ar] = vb.y;
        As[ac0 + 6][ar] = vb.z; As[ac0 + 7][ar] = vb.w;
        *(float4*)&B1s[br][bc * 4] = b1v;
        *(float4*)&B3s[br][bc * 4] = b3v;
        __syncthreads();

#pragma unroll
        for (int k = 0; k < 16; k++) {
            float a[8], b1[4], b3[4];
            *(float4*)&a[0] = *(const float4*)&As[k][tm * 8];
            *(float4*)&a[4] = *(const float4*)&As[k][tm * 8 + 4];
            *(float4*)&b1[0] = *(const float4*)&B1s[k][tn * 4];
            *(float4*)&b3[0] = *(const float4*)&B3s[k][tn * 4];
#pragma unroll
            for (int i = 0; i < 8; i++)
#pragma unroll
                for (int j = 0; j < 4; j++) {
                    acc1[i][j] += a[i] * b1[j];
                    acc3[i][j] += a[i] * b3[j];
                }
        }
    }

    float* hbase = g_h + (size_t)e * T_TOK * H_DIM;
#pragma unroll
    for (int i = 0; i < 8; i++) {
        const int m = m0 + tm * 8 + i;
        if (m < cnt) {
            float4 hv;
            float g, u;
            g = acc1[i][0]; u = acc3[i][0]; hv.x = (g / (1.f + expf(-g))) * u;
            g = acc1[i][1]; u = acc3[i][1]; hv.y = (g / (1.f + expf(-g))) * u;
            g = acc1[i][2]; u = acc3[i][2]; hv.z = (g / (1.f + expf(-g))) * u;
            g = acc1[i][3]; u = acc3[i][3]; hv.w = (g / (1.f + expf(-g))) * u;
            *(float4*)&hbase[(size_t)m * H_DIM + n0 + tn * 4] = hv;
        }
    }
}

// ---------------- down-proj GEMM with combine-weight epilogue ----------------
// Per expert: down[m, n] = w_m * (H[m] @ w2[e]),  K = H_DIM.
__global__ __launch_bounds__(256) void gemm2_kernel(const float* __restrict__ w2) {
    const int e   = blockIdx.z;
    const int cnt = g_cnt[e];
    const int m0  = blockIdx.y * 128;
    if (m0 >= cnt) return;
    const int n0  = blockIdx.x * 64;

    __shared__ float As[16][128];
    __shared__ float Bs[16][64];

    const int tid = threadIdx.x;
    const int ar  = tid >> 1;
    const int ac0 = (tid & 1) * 8;
    const int mrow = (m0 + ar < cnt) ? (m0 + ar) : (cnt - 1);
    const float* hrow = g_h + ((size_t)e * T_TOK + mrow) * H_DIM + ac0;

    const int br = tid >> 4;
    const int bc = tid & 15;
    const float* w2p = w2 + ((size_t)e * H_DIM + br) * D_DIM + n0 + bc * 4;

    const int tm = tid >> 4;
    const int tn = tid & 15;

    float acc[8][4];
#pragma unroll
    for (int i = 0; i < 8; i++)
#pragma unroll
        for (int j = 0; j < 4; j++) acc[i][j] = 0.f;

    for (int k0 = 0; k0 < H_DIM; k0 += 16) {
        const float4 va = *(const float4*)(hrow + k0);
        const float4 vb = *(const float4*)(hrow + k0 + 4);
        const float4 bv = *(const float4*)(w2p + (size_t)k0 * D_DIM);

        __syncthreads();
        As[ac0 + 0][ar] = va.x; As[ac0 + 1][ar] = va.y;
        As[ac0 + 2][ar] = va.z; As[ac0 + 3][ar] = va.w;
        As[ac0 + 4][ar] = vb.x; As[ac0 + 5][ar] = vb.y;
        As[ac0 + 6][ar] = vb.z; As[ac0 + 7][ar] = vb.w;
        *(float4*)&Bs[br][bc * 4] = bv;
        __syncthreads();

#pragma unroll
        for (int k = 0; k < 16; k++) {
            float a[8], b[4];
            *(float4*)&a[0] = *(const float4*)&As[k][tm * 8];
            *(float4*)&a[4] = *(const float4*)&As[k][tm * 8 + 4];
            *(float4*)&b[0] = *(const float4*)&Bs[k][tn * 4];
#pragma unroll
            for (int i = 0; i < 8; i++)
#pragma unroll
                for (int j = 0; j < 4; j++) acc[i][j] += a[i] * b[j];
        }
    }

#pragma unroll
    for (int i = 0; i < 8; i++) {
        const int m = m0 + tm * 8 + i;
        if (m < cnt) {
            const float wgt = g_slot_w[e * T_TOK + m];
            float4 ov;
            ov.x = acc[i][0] * wgt; ov.y = acc[i][1] * wgt;
            ov.z = acc[i][2] * wgt; ov.w = acc[i][3] * wgt;
            *(float4*)&g_down[((size_t)e * T_TOK + m) * D_DIM + n0 + tn * 4] = ov;
        }
    }
}

// ---------------- combine: out[t] = down[slot0] + down[slot1] ----------------
__global__ __launch_bounds__(256) void combine_kernel(float* __restrict__ out) {
    const int t = blockIdx.x;
    const int i = threadIdx.x;  // D/4 = 256 float4 per token
    const int s0 = g_tok_slot[2 * t + 0];
    const int s1 = g_tok_slot[2 * t + 1];
    const float4 a = *(const float4*)(g_down + (size_t)s0 * D_DIM + i * 4);
    const float4 b = *(const float4*)(g_down + (size_t)s1 * D_DIM + i * 4);
    float4 o;
    o.x = a.x + b.x; o.y = a.y + b.y; o.z = a.z + b.z; o.w = a.w + b.w;
    *(float4*)(out + (size_t)t * D_DIM + i * 4) = o;
}

// ---------------- launch ----------------
extern "C" void kernel_launch(void* const* d_in, const int* in_sizes, int n_in,
                              void* d_out, int out_size) {
    const float* x  = (const float*)d_in[0];
    const float* wg = (const float*)d_in[1];
    const float* w1 = (const float*)d_in[2];
    const float* w2 = (const float*)d_in[3];
    const float* w3 = (const float*)d_in[4];
    float* out = (float*)d_out;

    zero_cnt_kernel<<<1, 32>>>();
    gating_kernel<<<T_TOK, 256>>>(x, wg);
    gemm13_kernel<<<dim3(H_DIM / 64, T_TOK / 128, E_NUM), 256>>>(x, w1, w3);
    gemm2_kernel<<<dim3(D_DIM / 64, T_TOK / 128, E_NUM), 256>>>(w2);
    combine_kernel<<<T_TOK, 256>>>(out);
}

// round 4
// speedup vs baseline: 1.8294x; 1.8290x over previous
#include <cuda_runtime.h>
#include <math.h>
#include <stdint.h>

#define T_TOK 4096
#define D_DIM 1024
#define E_NUM 8
#define H_DIM 2816

__device__ int   g_cnt[E_NUM];
__device__ int   g_slot_tok[E_NUM * T_TOK];
__device__ float g_slot_w[E_NUM * T_TOK];
__device__ int   g_tok_slot[T_TOK * 2];
__device__ float g_h[(size_t)E_NUM * T_TOK * H_DIM];
__device__ float g_down[(size_t)E_NUM * T_TOK * D_DIM];

// ---------------- helpers ----------------
__device__ __forceinline__ uint32_t f2tf(float f){
    uint32_t r; asm("cvt.rna.tf32.f32 %0, %1;" : "=r"(r) : "f"(f)); return r;
}
__device__ __forceinline__ void mma8(float* c, const uint32_t* a, const uint32_t* b){
    asm volatile("mma.sync.aligned.m16n8k8.row.col.f32.tf32.tf32.f32 "
        "{%0,%1,%2,%3}, {%4,%5,%6,%7}, {%8,%9}, {%0,%1,%2,%3};"
        : "+f"(c[0]), "+f"(c[1]), "+f"(c[2]), "+f"(c[3])
        : "r"(a[0]), "r"(a[1]), "r"(a[2]), "r"(a[3]), "r"(b[0]), "r"(b[1]));
}
__device__ __forceinline__ float silu_mul(float g, float u){
    return (g / (1.f + expf(-g))) * u;
}

// ---------------- small kernels ----------------
__global__ void zero_cnt_kernel() { if (threadIdx.x < E_NUM) g_cnt[threadIdx.x] = 0; }

__global__ __launch_bounds__(256) void gating_kernel(const float* __restrict__ x,
                                                     const float* __restrict__ wg){
    __shared__ float s_red[E_NUM][256];
    const int t = blockIdx.x, tid = threadIdx.x;
    const float* xr = x + (size_t)t * D_DIM;
    float part[E_NUM];
#pragma unroll
    for (int e = 0; e < E_NUM; e++) part[e] = 0.f;
    for (int d = tid; d < D_DIM; d += 256) {
        const float xv = xr[d];
        const float* w = wg + (size_t)d * E_NUM;
#pragma unroll
        for (int e = 0; e < E_NUM; e++) part[e] += xv * w[e];
    }
#pragma unroll
    for (int e = 0; e < E_NUM; e++) s_red[e][tid] = part[e];
    __syncthreads();
    for (int s = 128; s > 0; s >>= 1) {
        if (tid < s) {
#pragma unroll
            for (int e = 0; e < E_NUM; e++) s_red[e][tid] += s_red[e][tid + s];
        }
        __syncthreads();
    }
    if (tid == 0) {
        float p[E_NUM]; float mx = -1e30f;
#pragma unroll
        for (int e = 0; e < E_NUM; e++) mx = fmaxf(mx, s_red[e][0]);
#pragma unroll
        for (int e = 0; e < E_NUM; e++) p[e] = expf(s_red[e][0] - mx);
        int i1 = 0;
#pragma unroll
        for (int e = 1; e < E_NUM; e++) if (p[e] > p[i1]) i1 = e;
        int i2 = (i1 == 0) ? 1 : 0;
#pragma unroll
        for (int e = 0; e < E_NUM; e++) if (e != i1 && p[e] > p[i2]) i2 = e;
        const float ws = p[i1] + p[i2];
        const int s0 = atomicAdd(&g_cnt[i1], 1);
        const int s1 = atomicAdd(&g_cnt[i2], 1);
        g_slot_tok[i1 * T_TOK + s0] = t;  g_slot_w[i1 * T_TOK + s0] = p[i1] / ws;
        g_slot_tok[i2 * T_TOK + s1] = t;  g_slot_w[i2 * T_TOK + s1] = p[i2] / ws;
        g_tok_slot[2 * t + 0] = i1 * T_TOK + s0;
        g_tok_slot[2 * t + 1] = i2 * T_TOK + s1;
    }
}

__global__ __launch_bounds__(256) void combine_kernel(float* __restrict__ out){
    const int t = blockIdx.x, i = threadIdx.x;
    const int s0 = g_tok_slot[2 * t + 0], s1 = g_tok_slot[2 * t + 1];
    const float4 a = *(const float4*)(g_down + (size_t)s0 * D_DIM + i * 4);
    const float4 b = *(const float4*)(g_down + (size_t)s1 * D_DIM + i * 4);
    float4 o; o.x = a.x + b.x; o.y = a.y + b.y; o.z = a.z + b.z; o.w = a.w + b.w;
    *(float4*)(out + (size_t)t * D_DIM + i * 4) = o;
}

// ---------------- gemm13 (mma.sync tf32): h = silu(X@w1) * (X@w3) ----------------
// BM=128, BN=64 (per matrix), BK=32. 256 threads = 8 warps (4M x 2N), warp tile 32x32.
__global__ __launch_bounds__(256) void gemm13_mma(const float* __restrict__ x,
                                                  const float* __restrict__ w1,
                                                  const float* __restrict__ w3){
    const int e = blockIdx.z, cnt = g_cnt[e], m0 = blockIdx.y * 128;
    if (m0 >= cnt) return;
    const int n0 = blockIdx.x * 64;

    __shared__ uint32_t As[128][36];
    __shared__ uint32_t B1s[32][68];
    __shared__ uint32_t B3s[32][68];
    __shared__ int s_row[128];

    const int tid = threadIdx.x, wid = tid >> 5, lane = tid & 31;
    const int gq = lane >> 2, tq = lane & 3;
    const int warp_m = (wid & 3) * 32, warp_n = (wid >> 2) * 32;

    if (tid < 128) s_row[tid] = g_slot_tok[e * T_TOK + min(m0 + tid, cnt - 1)];
    __syncthreads();

    // A: thread -> row tid>>1, k-half (tid&1)*16 (4 float4 along k)
    const int am = tid >> 1, akh = (tid & 1) * 16;
    const float* xrow = x + (size_t)s_row[am] * D_DIM + akh;
    // B: thread -> k row tid>>3, n quads (tid&7)*4 and +32
    const int bk = tid >> 3, bn = (tid & 7) * 4;
    const float* w1p = w1 + ((size_t)e * D_DIM + bk) * H_DIM + n0 + bn;
    const float* w3p = w3 + ((size_t)e * D_DIM + bk) * H_DIM + n0 + bn;

    float accg[2][4][4], accu[2][4][4];
#pragma unroll
    for (int i = 0; i < 2; i++)
#pragma unroll
        for (int j = 0; j < 4; j++)
#pragma unroll
            for (int q = 0; q < 4; q++) { accg[i][j][q] = 0.f; accu[i][j][q] = 0.f; }

    float4 ra[4], rb1[2], rb3[2];
    // prologue: load chunk 0
#pragma unroll
    for (int i = 0; i < 4; i++) ra[i] = *(const float4*)(xrow + i * 4);
    rb1[0] = *(const float4*)(w1p);      rb1[1] = *(const float4*)(w1p + 32);
    rb3[0] = *(const float4*)(w3p);      rb3[1] = *(const float4*)(w3p + 32);

    const int NC = D_DIM / 32;
    for (int c = 0; c < NC; c++) {
        __syncthreads();
#pragma unroll
        for (int i = 0; i < 4; i++) {
            As[am][akh + i * 4 + 0] = f2tf(ra[i].x);
            As[am][akh + i * 4 + 1] = f2tf(ra[i].y);
            As[am][akh + i * 4 + 2] = f2tf(ra[i].z);
            As[am][akh + i * 4 + 3] = f2tf(ra[i].w);
        }
        B1s[bk][bn + 0] = f2tf(rb1[0].x); B1s[bk][bn + 1] = f2tf(rb1[0].y);
        B1s[bk][bn + 2] = f2tf(rb1[0].z); B1s[bk][bn + 3] = f2tf(rb1[0].w);
        B1s[bk][bn + 32] = f2tf(rb1[1].x); B1s[bk][bn + 33] = f2tf(rb1[1].y);
        B1s[bk][bn + 34] = f2tf(rb1[1].z); B1s[bk][bn + 35] = f2tf(rb1[1].w);
        B3s[bk][bn + 0] = f2tf(rb3[0].x); B3s[bk][bn + 1] = f2tf(rb3[0].y);
        B3s[bk][bn + 2] = f2tf(rb3[0].z); B3s[bk][bn + 3] = f2tf(rb3[0].w);
        B3s[bk][bn + 32] = f2tf(rb3[1].x); B3s[bk][bn + 33] = f2tf(rb3[1].y);
        B3s[bk][bn + 34] = f2tf(rb3[1].z); B3s[bk][bn + 35] = f2tf(rb3[1].w);
        __syncthreads();

        if (c + 1 < NC) {
            const int k0g = (c + 1) * 32;
#pragma unroll
            for (int i = 0; i < 4; i++) ra[i] = *(const float4*)(xrow + k0g + i * 4);
            const float* p1 = w1p + (size_t)k0g * H_DIM;
            const float* p3 = w3p + (size_t)k0g * H_DIM;
            rb1[0] = *(const float4*)(p1); rb1[1] = *(const float4*)(p1 + 32);
            rb3[0] = *(const float4*)(p3); rb3[1] = *(const float4*)(p3 + 32);
        }

#pragma unroll
        for (int ks = 0; ks < 4; ks++) {
            const int k0 = ks * 8;
            uint32_t af[2][4];
#pragma unroll
            for (int i = 0; i < 2; i++) {
                const int m = warp_m + i * 16;
                af[i][0] = As[m + gq][k0 + tq];
                af[i][1] = As[m + gq + 8][k0 + tq];
                af[i][2] = As[m + gq][k0 + tq + 4];
                af[i][3] = As[m + gq + 8][k0 + tq + 4];
            }
#pragma unroll
            for (int j = 0; j < 4; j++) {
                const int n = warp_n + j * 8;
                uint32_t b1f[2] = { B1s[k0 + tq][n + gq], B1s[k0 + tq + 4][n + gq] };
                uint32_t b3f[2] = { B3s[k0 + tq][n + gq], B3s[k0 + tq + 4][n + gq] };
#pragma unroll
                for (int i = 0; i < 2; i++) {
                    mma8(accg[i][j], af[i], b1f);
                    mma8(accu[i][j], af[i], b3f);
                }
            }
        }
    }

    // epilogue: h = silu(gate)*up -> g_h
    float* hb = g_h + ((size_t)e * T_TOK + m0) * H_DIM + n0;
#pragma unroll
    for (int i = 0; i < 2; i++) {
        const int r0 = warp_m + i * 16 + gq;
        const int r1 = r0 + 8;
#pragma unroll
        for (int j = 0; j < 4; j++) {
            const int col = warp_n + j * 8 + tq * 2;
            if (m0 + r0 < cnt) {
                float2 o;
                o.x = silu_mul(accg[i][j][0], accu[i][j][0]);
                o.y = silu_mul(accg[i][j][1], accu[i][j][1]);
                *(float2*)(hb + (size_t)r0 * H_DIM + col) = o;
            }
            if (m0 + r1 < cnt) {
                float2 o;
                o.x = silu_mul(accg[i][j][2], accu[i][j][2]);
                o.y = silu_mul(accg[i][j][3], accu[i][j][3]);
                *(float2*)(hb + (size_t)r1 * H_DIM + col) = o;
            }
        }
    }
}

// ---------------- gemm2 (mma.sync tf32): down = w_m * (H @ w2) ----------------
__global__ __launch_bounds__(256) void gemm2_mma(const float* __restrict__ w2){
    const int e = blockIdx.z, cnt = g_cnt[e], m0 = blockIdx.y * 128;
    if (m0 >= cnt) return;
    const int n0 = blockIdx.x * 64;

    __shared__ uint32_t As[128][36];
    __shared__ uint32_t Bs[32][68];

    const int tid = threadIdx.x, wid = tid >> 5, lane = tid & 31;
    const int gq = lane >> 2, tq = lane & 3;
    const int warp_m = (wid & 3) * 32, warp_n = (wid >> 2) * 32;

    const int am = tid >> 1, akh = (tid & 1) * 16;
    const float* hrow = g_h + ((size_t)e * T_TOK + min(m0 + am, cnt - 1)) * H_DIM + akh;
    const int bk = tid >> 3, bn = (tid & 7) * 4;
    const float* w2p = w2 + ((size_t)e * H_DIM + bk) * D_DIM + n0 + bn;

    float acc[2][4][4];
#pragma unroll
    for (int i = 0; i < 2; i++)
#pragma unroll
        for (int j = 0; j < 4; j++)
#pragma unroll
            for (int q = 0; q < 4; q++) acc[i][j][q] = 0.f;

    float4 ra[4], rb[2];
#pragma unroll
    for (int i = 0; i < 4; i++) ra[i] = *(const float4*)(hrow + i * 4);
    rb[0] = *(const float4*)(w2p); rb[1] = *(const float4*)(w2p + 32);

    const int NC = H_DIM / 32;  // 88
    for (int c = 0; c < NC; c++) {
        __syncthreads();
#pragma unroll
        for (int i = 0; i < 4; i++) {
            As[am][akh + i * 4 + 0] = f2tf(ra[i].x);
            As[am][akh + i * 4 + 1] = f2tf(ra[i].y);
            As[am][akh + i * 4 + 2] = f2tf(ra[i].z);
            As[am][akh + i * 4 + 3] = f2tf(ra[i].w);
        }
        Bs[bk][bn + 0] = f2tf(rb[0].x); Bs[bk][bn + 1] = f2tf(rb[0].y);
        Bs[bk][bn + 2] = f2tf(rb[0].z); Bs[bk][bn + 3] = f2tf(rb[0].w);
        Bs[bk][bn + 32] = f2tf(rb[1].x); Bs[bk][bn + 33] = f2tf(rb[1].y);
        Bs[bk][bn + 34] = f2tf(rb[1].z); Bs[bk][bn + 35] = f2tf(rb[1].w);
        __syncthreads();

        if (c + 1 < NC) {
            const int k0g = (c + 1) * 32;
#pragma unroll
            for (int i = 0; i < 4; i++) ra[i] = *(const float4*)(hrow + k0g + i * 4);
            const float* p = w2p + (size_t)k0g * D_DIM;
            rb[0] = *(const float4*)(p); rb[1] = *(const float4*)(p + 32);
        }

#pragma unroll
        for (int ks = 0; ks < 4; ks++) {
            const int k0 = ks * 8;
            uint32_t af[2][4];
#pragma unroll
            for (int i = 0; i < 2; i++) {
                const int m = warp_m + i * 16;
                af[i][0] = As[m + gq][k0 + tq];
                af[i][1] = As[m + gq + 8][k0 + tq];
                af[i][2] = As[m + gq][k0 + tq + 4];
                af[i][3] = As[m + gq + 8][k0 + tq + 4];
            }
#pragma unroll
            for (int j = 0; j < 4; j++) {
                const int n = warp_n + j * 8;
                uint32_t bf[2] = { Bs[k0 + tq][n + gq], Bs[k0 + tq + 4][n + gq] };
#pragma unroll
                for (int i = 0; i < 2; i++) mma8(acc[i][j], af[i], bf);
            }
        }
    }

    float* db = g_down + ((size_t)e * T_TOK + m0) * D_DIM + n0;
#pragma unroll
    for (int i = 0; i < 2; i++) {
        const int r0 = warp_m + i * 16 + gq;
        const int r1 = r0 + 8;
        const float wg0 = g_slot_w[e * T_TOK + min(m0 + r0, cnt - 1)];
        const float wg1 = g_slot_w[e * T_TOK + min(m0 + r1, cnt - 1)];
#pragma unroll
        for (int j = 0; j < 4; j++) {
            const int col = warp_n + j * 8 + tq * 2;
            if (m0 + r0 < cnt) {
                float2 o; o.x = acc[i][j][0] * wg0; o.y = acc[i][j][1] * wg0;
                *(float2*)(db + (size_t)r0 * D_DIM + col) = o;
            }
            if (m0 + r1 < cnt) {
                float2 o; o.x = acc[i][j][2] * wg1; o.y = acc[i][j][3] * wg1;
                *(float2*)(db + (size_t)r1 * D_DIM + col) = o;
            }
        }
    }
}

// ---------------- launch ----------------
extern "C" void kernel_launch(void* const* d_in, const int* in_sizes, int n_in,
                              void* d_out, int out_size){
    const float* x  = (const float*)d_in[0];
    const float* wg = (const float*)d_in[1];
    const float* w1 = (const float*)d_in[2];
    const float* w2 = (const float*)d_in[3];
    const float* w3 = (const float*)d_in[4];
    float* out = (float*)d_out;

    zero_cnt_kernel<<<1, 32>>>();
    gating_kernel<<<T_TOK, 256>>>(x, wg);
    gemm13_mma<<<dim3(H_DIM / 64, T_TOK / 128, E_NUM), 256>>>(x, w1, w3);
    gemm2_mma<<<dim3(D_DIM / 64, T_TOK / 128, E_NUM), 256>>>(w2);
    combine_kernel<<<T_TOK, 256>>>(out);
}

// round 5
// speedup vs baseline: 2.4705x; 1.3505x over previous
#include <cuda_runtime.h>
#include <math.h>
#include <stdint.h>

#define T_TOK 4096
#define D_DIM 1024
#define E_NUM 8
#define H_DIM 2816

__device__ int   g_cnt[E_NUM];
__device__ int   g_slot_tok[E_NUM * T_TOK];
__device__ float g_slot_w[E_NUM * T_TOK];
__device__ int   g_tok_slot[T_TOK * 2];
__device__ float g_h[(size_t)E_NUM * T_TOK * H_DIM];
__device__ float g_down[(size_t)E_NUM * T_TOK * D_DIM];

// ---------------- helpers ----------------
__device__ __forceinline__ uint32_t f2tf(float f){
    uint32_t r; asm("cvt.rna.tf32.f32 %0, %1;" : "=r"(r) : "f"(f)); return r;
}
__device__ __forceinline__ void mma8(float* c, const uint32_t* a, const uint32_t* b){
    asm volatile("mma.sync.aligned.m16n8k8.row.col.f32.tf32.tf32.f32 "
        "{%0,%1,%2,%3}, {%4,%5,%6,%7}, {%8,%9}, {%0,%1,%2,%3};"
        : "+f"(c[0]), "+f"(c[1]), "+f"(c[2]), "+f"(c[3])
        : "r"(a[0]), "r"(a[1]), "r"(a[2]), "r"(a[3]), "r"(b[0]), "r"(b[1]));
}
__device__ __forceinline__ float silu_mul(float g, float u){
    return (g / (1.f + expf(-g))) * u;
}
__device__ __forceinline__ uint4 cvt4(float4 v){
    uint4 u; u.x = f2tf(v.x); u.y = f2tf(v.y); u.z = f2tf(v.z); u.w = f2tf(v.w); return u;
}

// ---------------- small kernels ----------------
__global__ void zero_cnt_kernel() { if (threadIdx.x < E_NUM) g_cnt[threadIdx.x] = 0; }

__global__ __launch_bounds__(256) void gating_kernel(const float* __restrict__ x,
                                                     const float* __restrict__ wg){
    __shared__ float s_red[E_NUM][256];
    const int t = blockIdx.x, tid = threadIdx.x;
    const float* xr = x + (size_t)t * D_DIM;
    float part[E_NUM];
#pragma unroll
    for (int e = 0; e < E_NUM; e++) part[e] = 0.f;
    for (int d = tid; d < D_DIM; d += 256) {
        const float xv = xr[d];
        const float* w = wg + (size_t)d * E_NUM;
#pragma unroll
        for (int e = 0; e < E_NUM; e++) part[e] += xv * w[e];
    }
#pragma unroll
    for (int e = 0; e < E_NUM; e++) s_red[e][tid] = part[e];
    __syncthreads();
    for (int s = 128; s > 0; s >>= 1) {
        if (tid < s) {
#pragma unroll
            for (int e = 0; e < E_NUM; e++) s_red[e][tid] += s_red[e][tid + s];
        }
        __syncthreads();
    }
    if (tid == 0) {
        float p[E_NUM]; float mx = -1e30f;
#pragma unroll
        for (int e = 0; e < E_NUM; e++) mx = fmaxf(mx, s_red[e][0]);
#pragma unroll
        for (int e = 0; e < E_NUM; e++) p[e] = expf(s_red[e][0] - mx);
        int i1 = 0;
#pragma unroll
        for (int e = 1; e < E_NUM; e++) if (p[e] > p[i1]) i1 = e;
        int i2 = (i1 == 0) ? 1 : 0;
#pragma unroll
        for (int e = 0; e < E_NUM; e++) if (e != i1 && p[e] > p[i2]) i2 = e;
        const float ws = p[i1] + p[i2];
        const int s0 = atomicAdd(&g_cnt[i1], 1);
        const int s1 = atomicAdd(&g_cnt[i2], 1);
        g_slot_tok[i1 * T_TOK + s0] = t;  g_slot_w[i1 * T_TOK + s0] = p[i1] / ws;
        g_slot_tok[i2 * T_TOK + s1] = t;  g_slot_w[i2 * T_TOK + s1] = p[i2] / ws;
        g_tok_slot[2 * t + 0] = i1 * T_TOK + s0;
        g_tok_slot[2 * t + 1] = i2 * T_TOK + s1;
    }
}

__global__ __launch_bounds__(256) void combine_kernel(float* __restrict__ out){
    const int t = blockIdx.x, i = threadIdx.x;
    const int s0 = g_tok_slot[2 * t + 0], s1 = g_tok_slot[2 * t + 1];
    const float4 a = *(const float4*)(g_down + (size_t)s0 * D_DIM + i * 4);
    const float4 b = *(const float4*)(g_down + (size_t)s1 * D_DIM + i * 4);
    float4 o; o.x = a.x + b.x; o.y = a.y + b.y; o.z = a.z + b.z; o.w = a.w + b.w;
    *(float4*)(out + (size_t)t * D_DIM + i * 4) = o;
}

// ---------------- gemm13: h = silu(X@w1) * (X@w3) ----------------
// BM=128, BN=64 per matrix, BK=32. 128 threads = 4 warps (2M x 2N),
// warp tile 64x32 per matrix (64x64 of work incl. both matrices).
__global__ __launch_bounds__(128, 2) void gemm13_mma(const float* __restrict__ x,
                                                     const float* __restrict__ w1,
                                                     const float* __restrict__ w3){
    const int e = blockIdx.z, cnt = g_cnt[e], m0 = blockIdx.y * 128;
    if (m0 >= cnt) return;
    const int n0 = blockIdx.x * 64;

    __shared__ uint32_t As[128][36];
    __shared__ uint32_t B1s[32][68];
    __shared__ uint32_t B3s[32][68];
    __shared__ int s_row[128];

    const int tid = threadIdx.x, wid = tid >> 5, lane = tid & 31;
    const int gq = lane >> 2, tq = lane & 3;
    const int warp_m = (wid & 1) * 64, warp_n = (wid >> 1) * 32;

    s_row[tid] = g_slot_tok[e * T_TOK + min(m0 + tid, cnt - 1)];
    __syncthreads();

    // A staging: thread handles rows arow+rr*32 (rr=0..3), k cols ak0..ak0+7
    const int arow = tid >> 2, ak0 = (tid & 3) * 8;
    const float* xA[4];
#pragma unroll
    for (int rr = 0; rr < 4; rr++)
        xA[rr] = x + (size_t)s_row[arow + rr * 32] * D_DIM + ak0;

    // B staging: k rows bkk, bkk+16; cols bn0..bn0+7
    const int bkk = tid >> 3, bn0 = (tid & 7) * 8;
    const float* w1b = w1 + ((size_t)e * D_DIM + bkk) * H_DIM + n0 + bn0;
    const float* w3b = w3 + ((size_t)e * D_DIM + bkk) * H_DIM + n0 + bn0;

    float accg[4][4][4], accu[4][4][4];
#pragma unroll
    for (int i = 0; i < 4; i++)
#pragma unroll
        for (int j = 0; j < 4; j++)
#pragma unroll
            for (int q = 0; q < 4; q++) { accg[i][j][q] = 0.f; accu[i][j][q] = 0.f; }

    const int NC = D_DIM / 32;
    for (int c = 0; c < NC; c++) {
        const int kg = c * 32;
        float4 va[4][2];
#pragma unroll
        for (int rr = 0; rr < 4; rr++) {
            va[rr][0] = *(const float4*)(xA[rr] + kg);
            va[rr][1] = *(const float4*)(xA[rr] + kg + 4);
        }
        float4 v1[2][2], v3[2][2];
#pragma unroll
        for (int pp = 0; pp < 2; pp++) {
            const float* p1 = w1b + (size_t)(kg + pp * 16) * H_DIM;
            const float* p3 = w3b + (size_t)(kg + pp * 16) * H_DIM;
            v1[pp][0] = *(const float4*)(p1); v1[pp][1] = *(const float4*)(p1 + 4);
            v3[pp][0] = *(const float4*)(p3); v3[pp][1] = *(const float4*)(p3 + 4);
        }
        __syncthreads();
#pragma unroll
        for (int rr = 0; rr < 4; rr++) {
            *(uint4*)&As[arow + rr * 32][ak0]     = cvt4(va[rr][0]);
            *(uint4*)&As[arow + rr * 32][ak0 + 4] = cvt4(va[rr][1]);
        }
#pragma unroll
        for (int pp = 0; pp < 2; pp++) {
            *(uint4*)&B1s[bkk + pp * 16][bn0]     = cvt4(v1[pp][0]);
            *(uint4*)&B1s[bkk + pp * 16][bn0 + 4] = cvt4(v1[pp][1]);
            *(uint4*)&B3s[bkk + pp * 16][bn0]     = cvt4(v3[pp][0]);
            *(uint4*)&B3s[bkk + pp * 16][bn0 + 4] = cvt4(v3[pp][1]);
        }
        __syncthreads();

#pragma unroll
        for (int ks = 0; ks < 4; ks++) {
            const int k0 = ks * 8;
            uint32_t af[4][4];
#pragma unroll
            for (int i = 0; i < 4; i++) {
                const int m = warp_m + i * 16;
                af[i][0] = As[m + gq][k0 + tq];
                af[i][1] = As[m + gq + 8][k0 + tq];
                af[i][2] = As[m + gq][k0 + tq + 4];
                af[i][3] = As[m + gq + 8][k0 + tq + 4];
            }
#pragma unroll
            for (int j = 0; j < 4; j++) {
                const int n = warp_n + j * 8;
                uint32_t b1f[2] = { B1s[k0 + tq][n + gq], B1s[k0 + tq + 4][n + gq] };
                uint32_t b3f[2] = { B3s[k0 + tq][n + gq], B3s[k0 + tq + 4][n + gq] };
#pragma unroll
                for (int i = 0; i < 4; i++) {
                    mma8(accg[i][j], af[i], b1f);
                    mma8(accu[i][j], af[i], b3f);
                }
            }
        }
    }

    float* hb = g_h + ((size_t)e * T_TOK + m0) * H_DIM + n0;
#pragma unroll
    for (int i = 0; i < 4; i++) {
        const int r0 = warp_m + i * 16 + gq;
        const int r1 = r0 + 8;
#pragma unroll
        for (int j = 0; j < 4; j++) {
            const int col = warp_n + j * 8 + tq * 2;
            if (m0 + r0 < cnt) {
                float2 o;
                o.x = silu_mul(accg[i][j][0], accu[i][j][0]);
                o.y = silu_mul(accg[i][j][1], accu[i][j][1]);
                *(float2*)(hb + (size_t)r0 * H_DIM + col) = o;
            }
            if (m0 + r1 < cnt) {
                float2 o;
                o.x = silu_mul(accg[i][j][2], accu[i][j][2]);
                o.y = silu_mul(accg[i][j][3], accu[i][j][3]);
                *(float2*)(hb + (size_t)r1 * H_DIM + col) = o;
            }
        }
    }
}

// ---------------- gemm2: down = w_m * (H @ w2) ----------------
// BM=128, BN=128, BK=32. 128 threads = 4 warps (2M x 2N), warp tile 64x64.
__global__ __launch_bounds__(128, 2) void gemm2_mma(const float* __restrict__ w2){
    const int e = blockIdx.z, cnt = g_cnt[e], m0 = blockIdx.y * 128;
    if (m0 >= cnt) return;
    const int n0 = blockIdx.x * 128;

    __shared__ uint32_t As[128][36];
    __shared__ uint32_t Bs[32][132];

    const int tid = threadIdx.x, wid = tid >> 5, lane = tid & 31;
    const int gq = lane >> 2, tq = lane & 3;
    const int warp_m = (wid & 1) * 64, warp_n = (wid >> 1) * 64;

    const int arow = tid >> 2, ak0 = (tid & 3) * 8;
    const float* hA[4];
#pragma unroll
    for (int rr = 0; rr < 4; rr++)
        hA[rr] = g_h + ((size_t)e * T_TOK + min(m0 + arow + rr * 32, cnt - 1)) * H_DIM + ak0;

    const int bkk = tid >> 3, bn0 = (tid & 7) * 16;
    const float* w2b = w2 + ((size_t)e * H_DIM + bkk) * D_DIM + n0 + bn0;

    float acc[4][8][4];
#pragma unroll
    for (int i = 0; i < 4; i++)
#pragma unroll
        for (int j = 0; j < 8; j++)
#pragma unroll
            for (int q = 0; q < 4; q++) acc[i][j][q] = 0.f;

    const int NC = H_DIM / 32;  // 88
    for (int c = 0; c < NC; c++) {
        const int kg = c * 32;
        float4 va[4][2];
#pragma unroll
        for (int rr = 0; rr < 4; rr++) {
            va[rr][0] = *(const float4*)(hA[rr] + kg);
            va[rr][1] = *(const float4*)(hA[rr] + kg + 4);
        }
        float4 vb[2][4];
#pragma unroll
        for (int pp = 0; pp < 2; pp++) {
            const float* p = w2b + (size_t)(kg + pp * 16) * D_DIM;
#pragma unroll
            for (int i = 0; i < 4; i++) vb[pp][i] = *(const float4*)(p + i * 4);
        }
        __syncthreads();
#pragma unroll
        for (int rr = 0; rr < 4; rr++) {
            *(uint4*)&As[arow + rr * 32][ak0]     = cvt4(va[rr][0]);
            *(uint4*)&As[arow + rr * 32][ak0 + 4] = cvt4(va[rr][1]);
        }
#pragma unroll
        for (int pp = 0; pp < 2; pp++)
#pragma unroll
            for (int i = 0; i < 4; i++)
                *(uint4*)&Bs[bkk + pp * 16][bn0 + i * 4] = cvt4(vb[pp][i]);
        __syncthreads();

#pragma unroll
        for (int ks = 0; ks < 4; ks++) {
            const int k0 = ks * 8;
            uint32_t af[4][4];
#pragma unroll
            for (int i = 0; i < 4; i++) {
                const int m = warp_m + i * 16;
                af[i][0] = As[m + gq][k0 + tq];
                af[i][1] = As[m + gq + 8][k0 + tq];
                af[i][2] = As[m + gq][k0 + tq + 4];
                af[i][3] = As[m + gq + 8][k0 + tq + 4];
            }
#pragma unroll
            for (int j = 0; j < 8; j++) {
                const int n = warp_n + j * 8;
                uint32_t bf[2] = { Bs[k0 + tq][n + gq], Bs[k0 + tq + 4][n + gq] };
#pragma unroll
                for (int i = 0; i < 4; i++) mma8(acc[i][j], af[i], bf);
            }
        }
    }

    float* db = g_down + ((size_t)e * T_TOK + m0) * D_DIM + n0;
#pragma unroll
    for (int i = 0; i < 4; i++) {
        const int r0 = warp_m + i * 16 + gq;
        const int r1 = r0 + 8;
        const float wg0 = g_slot_w[e * T_TOK + min(m0 + r0, cnt - 1)];
        const float wg1 = g_slot_w[e * T_TOK + min(m0 + r1, cnt - 1)];
#pragma unroll
        for (int j = 0; j < 8; j++) {
            const int col = warp_n + j * 8 + tq * 2;
            if (m0 + r0 < cnt) {
                float2 o; o.x = acc[i][j][0] * wg0; o.y = acc[i][j][1] * wg0;
                *(float2*)(db + (size_t)r0 * D_DIM + col) = o;
            }
            if (m0 + r1 < cnt) {
                float2 o; o.x = acc[i][j][2] * wg1; o.y = acc[i][j][3] * wg1;
                *(float2*)(db + (size_t)r1 * D_DIM + col) = o;
            }
        }
    }
}

// ---------------- launch ----------------
extern "C" void kernel_launch(void* const* d_in, const int* in_sizes, int n_in,
                              void* d_out, int out_size){
    const float* x  = (const float*)d_in[0];
    const float* wg = (const float*)d_in[1];
    const float* w1 = (const float*)d_in[2];
    const float* w2 = (const float*)d_in[3];
    const float* w3 = (const float*)d_in[4];
    float* out = (float*)d_out;

    zero_cnt_kernel<<<1, 32>>>();
    gating_kernel<<<T_TOK, 256>>>(x, wg);
    gemm13_mma<<<dim3(H_DIM / 64, T_TOK / 128, E_NUM), 128>>>(x, w1, w3);
    gemm2_mma<<<dim3(D_DIM / 128, T_TOK / 128, E_NUM), 128>>>(w2);
    combine_kernel<<<T_TOK, 256>>>(out);
}

// round 6
// speedup vs baseline: 2.5600x; 1.0362x over previous
#include <cuda_runtime.h>
#include <math.h>
#include <stdint.h>

#define T_TOK 4096
#define D_DIM 1024
#define E_NUM 8
#define H_DIM 2816

__device__ int   g_cnt[E_NUM];
__device__ int   g_slot_tok[E_NUM * T_TOK];
__device__ float g_slot_w[E_NUM * T_TOK];
__device__ int   g_tok_slot[T_TOK * 2];
__device__ float g_h[(size_t)E_NUM * T_TOK * H_DIM];
__device__ float g_down[(size_t)E_NUM * T_TOK * D_DIM];

// ---------------- helpers ----------------
__device__ __forceinline__ uint32_t smem_u32(const void* p){
    uint32_t a; asm("{ .reg .u64 t; cvta.to.shared.u64 t, %1; cvt.u32.u64 %0, t; }" : "=r"(a) : "l"(p)); return a;
}
__device__ __forceinline__ uint32_t tfo(uint32_t bits){
    uint32_t r; asm("cvt.rna.tf32.f32 %0, %1;" : "=r"(r) : "f"(__uint_as_float(bits))); return r;
}
__device__ __forceinline__ void mma8(float* c, const uint32_t* a, const uint32_t* b){
    asm volatile("mma.sync.aligned.m16n8k8.row.col.f32.tf32.tf32.f32 "
        "{%0,%1,%2,%3}, {%4,%5,%6,%7}, {%8,%9}, {%0,%1,%2,%3};"
        : "+f"(c[0]), "+f"(c[1]), "+f"(c[2]), "+f"(c[3])
        : "r"(a[0]), "r"(a[1]), "r"(a[2]), "r"(a[3]), "r"(b[0]), "r"(b[1]));
}
__device__ __forceinline__ float silu_mul(float g, float u){
    return (g / (1.f + expf(-g))) * u;
}
__device__ __forceinline__ void cpa16(uint32_t dst, const void* src){
    asm volatile("cp.async.cg.shared.global [%0], [%1], 16;" :: "r"(dst), "l"(src) : "memory");
}
#define CP_COMMIT() asm volatile("cp.async.commit_group;" ::: "memory")
#define CP_WAIT0()  asm volatile("cp.async.wait_group 0;" ::: "memory")

// ---------------- small kernels ----------------
__global__ void zero_cnt_kernel() { if (threadIdx.x < E_NUM) g_cnt[threadIdx.x] = 0; }

__global__ __launch_bounds__(256) void gating_kernel(const float* __restrict__ x,
                                                     const float* __restrict__ wg){
    __shared__ float s_red[E_NUM][256];
    const int t = blockIdx.x, tid = threadIdx.x;
    const float* xr = x + (size_t)t * D_DIM;
    float part[E_NUM];
#pragma unroll
    for (int e = 0; e < E_NUM; e++) part[e] = 0.f;
    for (int d = tid; d < D_DIM; d += 256) {
        const float xv = xr[d];
        const float* w = wg + (size_t)d * E_NUM;
#pragma unroll
        for (int e = 0; e < E_NUM; e++) part[e] += xv * w[e];
    }
#pragma unroll
    for (int e = 0; e < E_NUM; e++) s_red[e][tid] = part[e];
    __syncthreads();
    for (int s = 128; s > 0; s >>= 1) {
        if (tid < s) {
#pragma unroll
            for (int e = 0; e < E_NUM; e++) s_red[e][tid] += s_red[e][tid + s];
        }
        __syncthreads();
    }
    if (tid == 0) {
        float p[E_NUM]; float mx = -1e30f;
#pragma unroll
        for (int e = 0; e < E_NUM; e++) mx = fmaxf(mx, s_red[e][0]);
#pragma unroll
        for (int e = 0; e < E_NUM; e++) p[e] = expf(s_red[e][0] - mx);
        int i1 = 0;
#pragma unroll
        for (int e = 1; e < E_NUM; e++) if (p[e] > p[i1]) i1 = e;
        int i2 = (i1 == 0) ? 1 : 0;
#pragma unroll
        for (int e = 0; e < E_NUM; e++) if (e != i1 && p[e] > p[i2]) i2 = e;
        const float ws = p[i1] + p[i2];
        const int s0 = atomicAdd(&g_cnt[i1], 1);
        const int s1 = atomicAdd(&g_cnt[i2], 1);
        g_slot_tok[i1 * T_TOK + s0] = t;  g_slot_w[i1 * T_TOK + s0] = p[i1] / ws;
        g_slot_tok[i2 * T_TOK + s1] = t;  g_slot_w[i2 * T_TOK + s1] = p[i2] / ws;
        g_tok_slot[2 * t + 0] = i1 * T_TOK + s0;
        g_tok_slot[2 * t + 1] = i2 * T_TOK + s1;
    }
}

__global__ __launch_bounds__(256) void combine_kernel(float* __restrict__ out){
    const int t = blockIdx.x, i = threadIdx.x;
    const int s0 = g_tok_slot[2 * t + 0], s1 = g_tok_slot[2 * t + 1];
    const float4 a = *(const float4*)(g_down + (size_t)s0 * D_DIM + i * 4);
    const float4 b = *(const float4*)(g_down + (size_t)s1 * D_DIM + i * 4);
    float4 o; o.x = a.x + b.x; o.y = a.y + b.y; o.z = a.z + b.z; o.w = a.w + b.w;
    *(float4*)(out + (size_t)t * D_DIM + i * 4) = o;
}

// Dynamic SMEM layouts (uint32 words):
// gemm13 per buffer: A[128][36] (4608) | B1[32][68] (2176) | B3[32][68] (2176) = 8960 words
// gemm2  per buffer: A[128][36] (4608) | B[32][132] (4224)                     = 8832 words
#define BUF13_W 8960
#define B1_OFF  4608
#define B3_OFF  6784
#define BUF2_W  8832
#define B2_OFF  4608

extern __shared__ uint32_t dyn[];

// ---------------- gemm13: h = silu(X@w1) * (X@w3) ----------------
// BM=128, BN=64 per matrix, BK=32. 4 warps (2M x 2N), warp tile 64x32 per matrix.
__global__ __launch_bounds__(128, 2) void gemm13_mma(const float* __restrict__ x,
                                                     const float* __restrict__ w1,
                                                     const float* __restrict__ w3){
    const int e = blockIdx.z, cnt = g_cnt[e], m0 = blockIdx.y * 128;
    if (m0 >= cnt) return;
    const int n0 = blockIdx.x * 64;

    __shared__ int s_row[128];
    const uint32_t sbase = smem_u32(dyn);

    const int tid = threadIdx.x, wid = tid >> 5, lane = tid & 31;
    const int gq = lane >> 2, tq = lane & 3;
    const int warp_m = (wid & 1) * 64, warp_n = (wid >> 1) * 32;

    s_row[tid] = g_slot_tok[e * T_TOK + min(m0 + tid, cnt - 1)];
    __syncthreads();

    const int arow = tid >> 2, ak0 = (tid & 3) * 8;
    const float* xA[4];
#pragma unroll
    for (int rr = 0; rr < 4; rr++)
        xA[rr] = x + (size_t)s_row[arow + rr * 32] * D_DIM + ak0;

    const int bkk = tid >> 3, bn0 = (tid & 7) * 8;
    const float* w1b = w1 + ((size_t)e * D_DIM + bkk) * H_DIM + n0 + bn0;
    const float* w3b = w3 + ((size_t)e * D_DIM + bkk) * H_DIM + n0 + bn0;

    // per-thread cp.async destinations (byte offsets within a buffer)
    const uint32_t dA = sbase + (uint32_t)(arow * 36 + ak0) * 4;       // + rr*32*36*4
    const uint32_t dB1 = sbase + (uint32_t)(B1_OFF + bkk * 68 + bn0) * 4;  // + pp*16*68*4
    const uint32_t dB3 = sbase + (uint32_t)(B3_OFF + bkk * 68 + bn0) * 4;

    float accg[4][4][4], accu[4][4][4];
#pragma unroll
    for (int i = 0; i < 4; i++)
#pragma unroll
        for (int j = 0; j < 4; j++)
#pragma unroll
            for (int q = 0; q < 4; q++) { accg[i][j][q] = 0.f; accu[i][j][q] = 0.f; }

    const int NC = D_DIM / 32;

    // prologue: fill buffer 0 with chunk 0
    {
        const uint32_t bo = 0;
#pragma unroll
        for (int rr = 0; rr < 4; rr++) {
            cpa16(dA + bo + rr * (32 * 36 * 4),     xA[rr]);
            cpa16(dA + bo + rr * (32 * 36 * 4) + 16, xA[rr] + 4);
        }
#pragma unroll
        for (int pp = 0; pp < 2; pp++) {
            const float* p1 = w1b + (size_t)(pp * 16) * H_DIM;
            const float* p3 = w3b + (size_t)(pp * 16) * H_DIM;
            cpa16(dB1 + bo + pp * (16 * 68 * 4),      p1);
            cpa16(dB1 + bo + pp * (16 * 68 * 4) + 16, p1 + 4);
            cpa16(dB3 + bo + pp * (16 * 68 * 4),      p3);
            cpa16(dB3 + bo + pp * (16 * 68 * 4) + 16, p3 + 4);
        }
        CP_COMMIT();
    }

    for (int c = 0; c < NC; c++) {
        CP_WAIT0();
        __syncthreads();

        // issue fill for next chunk into the other buffer (overlaps MMA below)
        if (c + 1 < NC) {
            const uint32_t bo = (uint32_t)(((c + 1) & 1) * BUF13_W) * 4;
            const int kg = (c + 1) * 32;
#pragma unroll
            for (int rr = 0; rr < 4; rr++) {
                cpa16(dA + bo + rr * (32 * 36 * 4),      xA[rr] + kg);
                cpa16(dA + bo + rr * (32 * 36 * 4) + 16, xA[rr] + kg + 4);
            }
#pragma unroll
            for (int pp = 0; pp < 2; pp++) {
                const float* p1 = w1b + (size_t)(kg + pp * 16) * H_DIM;
                const float* p3 = w3b + (size_t)(kg + pp * 16) * H_DIM;
                cpa16(dB1 + bo + pp * (16 * 68 * 4),      p1);
                cpa16(dB1 + bo + pp * (16 * 68 * 4) + 16, p1 + 4);
                cpa16(dB3 + bo + pp * (16 * 68 * 4),      p3);
                cpa16(dB3 + bo + pp * (16 * 68 * 4) + 16, p3 + 4);
            }
        }
        CP_COMMIT();

        const uint32_t* Ab  = dyn + (c & 1) * BUF13_W;
        const uint32_t* B1b = Ab + B1_OFF;
        const uint32_t* B3b = Ab + B3_OFF;

#pragma unroll
        for (int ks = 0; ks < 4; ks++) {
            const int k0 = ks * 8;
            uint32_t af[4][4];
#pragma unroll
            for (int i = 0; i < 4; i++) {
                const int m = warp_m + i * 16;
                af[i][0] = tfo(Ab[(m + gq) * 36 + k0 + tq]);
                af[i][1] = tfo(Ab[(m + gq + 8) * 36 + k0 + tq]);
                af[i][2] = tfo(Ab[(m + gq) * 36 + k0 + tq + 4]);
                af[i][3] = tfo(Ab[(m + gq + 8) * 36 + k0 + tq + 4]);
            }
#pragma unroll
            for (int j = 0; j < 4; j++) {
                const int n = warp_n + j * 8;
                uint32_t b1f[2] = { tfo(B1b[(k0 + tq) * 68 + n + gq]), tfo(B1b[(k0 + tq + 4) * 68 + n + gq]) };
                uint32_t b3f[2] = { tfo(B3b[(k0 + tq) * 68 + n + gq]), tfo(B3b[(k0 + tq + 4) * 68 + n + gq]) };
#pragma unroll
                for (int i = 0; i < 4; i++) {
                    mma8(accg[i][j], af[i], b1f);
                    mma8(accu[i][j], af[i], b3f);
                }
            }
        }
    }

    float* hb = g_h + ((size_t)e * T_TOK + m0) * H_DIM + n0;
#pragma unroll
    for (int i = 0; i < 4; i++) {
        const int r0 = warp_m + i * 16 + gq;
        const int r1 = r0 + 8;
#pragma unroll
        for (int j = 0; j < 4; j++) {
            const int col = warp_n + j * 8 + tq * 2;
            if (m0 + r0 < cnt) {
                float2 o;
                o.x = silu_mul(accg[i][j][0], accu[i][j][0]);
                o.y = silu_mul(accg[i][j][1], accu[i][j][1]);
                *(float2*)(hb + (size_t)r0 * H_DIM + col) = o;
            }
            if (m0 + r1 < cnt) {
                float2 o;
                o.x = silu_mul(accg[i][j][2], accu[i][j][2]);
                o.y = silu_mul(accg[i][j][3], accu[i][j][3]);
                *(float2*)(hb + (size_t)r1 * H_DIM + col) = o;
            }
        }
    }
}

// ---------------- gemm2: down = w_m * (H @ w2) ----------------
// BM=128, BN=128, BK=32. 4 warps (2M x 2N), warp tile 64x64.
__global__ __launch_bounds__(128, 2) void gemm2_mma(const float* __restrict__ w2){
    const int e = blockIdx.z, cnt = g_cnt[e], m0 = blockIdx.y * 128;
    if (m0 >= cnt) return;
    const int n0 = blockIdx.x * 128;

    const uint32_t sbase = smem_u32(dyn);
    const int tid = threadIdx.x, wid = tid >> 5, lane = tid & 31;
    const int gq = lane >> 2, tq = lane & 3;
    const int warp_m = (wid & 1) * 64, warp_n = (wid >> 1) * 64;

    const int arow = tid >> 2, ak0 = (tid & 3) * 8;
    const float* hA[4];
#pragma unroll
    for (int rr = 0; rr < 4; rr++)
        hA[rr] = g_h + ((size_t)e * T_TOK + min(m0 + arow + rr * 32, cnt - 1)) * H_DIM + ak0;

    const int bkk = tid >> 3, bn0 = (tid & 7) * 16;
    const float* w2b = w2 + ((size_t)e * H_DIM + bkk) * D_DIM + n0 + bn0;

    const uint32_t dA = sbase + (uint32_t)(arow * 36 + ak0) * 4;
    const uint32_t dB = sbase + (uint32_t)(B2_OFF + bkk * 132 + bn0) * 4;

    float acc[4][8][4];
#pragma unroll
    for (int i = 0; i < 4; i++)
#pragma unroll
        for (int j = 0; j < 8; j++)
#pragma unroll
            for (int q = 0; q < 4; q++) acc[i][j][q] = 0.f;

    const int NC = H_DIM / 32;  // 88

    {
#pragma unroll
        for (int rr = 0; rr < 4; rr++) {
            cpa16(dA + rr * (32 * 36 * 4),      hA[rr]);
            cpa16(dA + rr * (32 * 36 * 4) + 16, hA[rr] + 4);
        }
#pragma unroll
        for (int pp = 0; pp < 2; pp++) {
            const float* p = w2b + (size_t)(pp * 16) * D_DIM;
#pragma unroll
            for (int i = 0; i < 4; i++)
                cpa16(dB + pp * (16 * 132 * 4) + i * 16, p + i * 4);
        }
        CP_COMMIT();
    }

    for (int c = 0; c < NC; c++) {
        CP_WAIT0();
        __syncthreads();

        if (c + 1 < NC) {
            const uint32_t bo = (uint32_t)(((c + 1) & 1) * BUF2_W) * 4;
            const int kg = (c + 1) * 32;
#pragma unroll
            for (int rr = 0; rr < 4; rr++) {
                cpa16(dA + bo + rr * (32 * 36 * 4),      hA[rr] + kg);
                cpa16(dA + bo + rr * (32 * 36 * 4) + 16, hA[rr] + kg + 4);
            }
#pragma unroll
            for (int pp = 0; pp < 2; pp++) {
                const float* p = w2b + (size_t)(kg + pp * 16) * D_DIM;
#pragma unroll
                for (int i = 0; i < 4; i++)
                    cpa16(dB + bo + pp * (16 * 132 * 4) + i * 16, p + i * 4);
            }
        }
        CP_COMMIT();

        const uint32_t* Ab = dyn + (c & 1) * BUF2_W;
        const uint32_t* Bb = Ab + B2_OFF;

#pragma unroll
        for (int ks = 0; ks < 4; ks++) {
            const int k0 = ks * 8;
            uint32_t af[4][4];
#pragma unroll
            for (int i = 0; i < 4; i++) {
                const int m = warp_m + i * 16;
                af[i][0] = tfo(Ab[(m + gq) * 36 + k0 + tq]);
                af[i][1] = tfo(Ab[(m + gq + 8) * 36 + k0 + tq]);
                af[i][2] = tfo(Ab[(m + gq) * 36 + k0 + tq + 4]);
                af[i][3] = tfo(Ab[(m + gq + 8) * 36 + k0 + tq + 4]);
            }
#pragma unroll
            for (int j = 0; j < 8; j++) {
                const int n = warp_n + j * 8;
                uint32_t bf[2] = { tfo(Bb[(k0 + tq) * 132 + n + gq]), tfo(Bb[(k0 + tq + 4) * 132 + n + gq]) };
#pragma unroll
                for (int i = 0; i < 4; i++) mma8(acc[i][j], af[i], bf);
            }
        }
    }

    float* db = g_down + ((size_t)e * T_TOK + m0) * D_DIM + n0;
#pragma unroll
    for (int i = 0; i < 4; i++) {
        const int r0 = warp_m + i * 16 + gq;
        const int r1 = r0 + 8;
        const float wg0 = g_slot_w[e * T_TOK + min(m0 + r0, cnt - 1)];
        const float wg1 = g_slot_w[e * T_TOK + min(m0 + r1, cnt - 1)];
#pragma unroll
        for (int j = 0; j < 8; j++) {
            const int col = warp_n + j * 8 + tq * 2;
            if (m0 + r0 < cnt) {
                float2 o; o.x = acc[i][j][0] * wg0; o.y = acc[i][j][1] * wg0;
                *(float2*)(db + (size_t)r0 * D_DIM + col) = o;
            }
            if (m0 + r1 < cnt) {
                float2 o; o.x = acc[i][j][2] * wg1; o.y = acc[i][j][3] * wg1;
                *(float2*)(db + (size_t)r1 * D_DIM + col) = o;
            }
        }
    }
}

// ---------------- launch ----------------
extern "C" void kernel_launch(void* const* d_in, const int* in_sizes, int n_in,
                              void* d_out, int out_size){
    const float* x  = (const float*)d_in[0];
    const float* wg = (const float*)d_in[1];
    const float* w1 = (const float*)d_in[2];
    const float* w2 = (const float*)d_in[3];
    const float* w3 = (const float*)d_in[4];
    float* out = (float*)d_out;

    const int smem13 = 2 * BUF13_W * 4;  // 71680
    const int smem2  = 2 * BUF2_W * 4;   // 70656
    cudaFuncSetAttribute(gemm13_mma, cudaFuncAttributeMaxDynamicSharedMemorySize, smem13);
    cudaFuncSetAttribute(gemm2_mma,  cudaFuncAttributeMaxDynamicSharedMemorySize, smem2);

    zero_cnt_kernel<<<1, 32>>>();
    gating_kernel<<<T_TOK, 256>>>(x, wg);
    gemm13_mma<<<dim3(H_DIM / 64, T_TOK / 128, E_NUM), 128, smem13>>>(x, w1, w3);
    gemm2_mma<<<dim3(D_DIM / 128, T_TOK / 128, E_NUM), 128, smem2>>>(w2);
    combine_kernel<<<T_TOK, 256>>>(out);
}